// round 1
// baseline (speedup 1.0000x reference)
#include <cuda_runtime.h>
#include <cuda_bf16.h>
#include <cstdint>

// Problem constants (fixed by the reference)
#define NN    100000      // nodes
#define DIN   512
#define DOUT  512

// Scratch: support = features @ W   (200 MB, __device__ global per harness rules)
__device__ float g_support[(size_t)NN * DOUT];

// Flag: 1 if rows/cols are int64, 0 if int32 (JAX x64-disabled fallback)
__device__ int g_idx_is64;

// ---------------------------------------------------------------------------
// Kernel 1: detect index dtype. int32 data read as int64 packs two random
// indices -> value >= NN almost surely within 2048 samples.
// ---------------------------------------------------------------------------
__global__ void detect_idx_kernel(const long long* __restrict__ rows, int n_edges)
{
    __shared__ int bad;
    if (threadIdx.x == 0) bad = 0;
    __syncthreads();
    int limit = 2048;
    if (limit > n_edges / 2) limit = n_edges / 2;   // int64 elems available if int32-packed
    for (int i = threadIdx.x; i < limit; i += blockDim.x) {
        long long v = rows[i];
        if (v < 0 || v >= NN) bad = 1;
    }
    __syncthreads();
    if (threadIdx.x == 0) g_idx_is64 = bad ? 0 : 1;
}

// ---------------------------------------------------------------------------
// Kernel 2: SGEMM  C[M,512] = A[M,512] * B[512,512], fp32.
// BM=BN=128, BK=8, TM=TN=8, 256 threads. Classic register-blocked SGEMM.
// ---------------------------------------------------------------------------
__global__ __launch_bounds__(256)
void sgemm_kernel(const float* __restrict__ A, const float* __restrict__ B,
                  float* __restrict__ C, int M)
{
    const int K = DIN, N = DOUT;
    __shared__ float As[8][128];
    __shared__ float Bs[8][128];

    const int tid = threadIdx.x;
    const int block_row = blockIdx.y;      // M tiles
    const int block_col = blockIdx.x;      // N tiles (4)

    // A-tile load mapping: 128 rows x 8 cols, one float4 per thread
    const int aRow = tid >> 1;             // 0..127
    const int aCol = (tid & 1) * 4;        // 0 or 4
    // B-tile load mapping: 8 rows x 128 cols, one float4 per thread
    const int bRow = tid >> 5;             // 0..7
    const int bCol = (tid & 31) * 4;       // 0..124
    // compute mapping: 16x16 threads of 8x8 micro-tiles
    const int tRow = (tid >> 4) * 8;
    const int tCol = (tid & 15) * 8;

    const long long gRow = (long long)block_row * 128 + aRow;
    const bool aValid = gRow < M;
    const float* Aptr = A + gRow * K;
    const float* Bptr = B + block_col * 128;

    float acc[8][8];
#pragma unroll
    for (int i = 0; i < 8; i++)
#pragma unroll
        for (int j = 0; j < 8; j++) acc[i][j] = 0.f;

    for (int k0 = 0; k0 < K; k0 += 8) {
        float4 a = aValid ? *(const float4*)(Aptr + k0 + aCol)
                          : make_float4(0.f, 0.f, 0.f, 0.f);
        As[aCol + 0][aRow] = a.x;
        As[aCol + 1][aRow] = a.y;
        As[aCol + 2][aRow] = a.z;
        As[aCol + 3][aRow] = a.w;
        float4 b = *(const float4*)(Bptr + (long long)(k0 + bRow) * N + bCol);
        *(float4*)&Bs[bRow][bCol] = b;
        __syncthreads();

#pragma unroll
        for (int k = 0; k < 8; k++) {
            float regM[8], regN[8];
#pragma unroll
            for (int i = 0; i < 8; i++) regM[i] = As[k][tRow + i];
#pragma unroll
            for (int j = 0; j < 8; j++) regN[j] = Bs[k][tCol + j];
#pragma unroll
            for (int i = 0; i < 8; i++)
#pragma unroll
                for (int j = 0; j < 8; j++) acc[i][j] += regM[i] * regN[j];
        }
        __syncthreads();
    }

#pragma unroll
    for (int i = 0; i < 8; i++) {
        long long r = (long long)block_row * 128 + tRow + i;
        if (r < M) {
            float* cp = C + r * N + block_col * 128 + tCol;
            *(float4*)(cp + 0) = make_float4(acc[i][0], acc[i][1], acc[i][2], acc[i][3]);
            *(float4*)(cp + 4) = make_float4(acc[i][4], acc[i][5], acc[i][6], acc[i][7]);
        }
    }
}

// ---------------------------------------------------------------------------
// Kernel 3: edge scatter. One warp per edge; 128 float4 per row, 4 iters.
// Vectorized no-return reduction: red.global.add.v4.f32 (sm_90+).
// ---------------------------------------------------------------------------
__global__ __launch_bounds__(256)
void scatter_kernel(const void* __restrict__ rows_, const void* __restrict__ cols_,
                    const float* __restrict__ vals, const float* __restrict__ sup,
                    float* __restrict__ out, int n_edges)
{
    const long long gwarp = ((long long)blockIdx.x * blockDim.x + threadIdx.x) >> 5;
    if (gwarp >= n_edges) return;
    const int lane = threadIdx.x & 31;
    const int e = (int)gwarp;

    long long r, c;
    if (g_idx_is64) {
        r = ((const long long*)rows_)[e];
        c = ((const long long*)cols_)[e];
    } else {
        r = (long long)((const int*)rows_)[e];
        c = (long long)((const int*)cols_)[e];
    }
    const float v = vals[e];

    const float4* __restrict__ src = (const float4*)(sup + c * DOUT);
    float4* __restrict__ dst = ((float4*)out) + r * (DOUT / 4);

#pragma unroll
    for (int i = 0; i < 4; i++) {
        const int idx = lane + i * 32;
        float4 s = src[idx];
        asm volatile("red.global.add.v4.f32 [%0], {%1, %2, %3, %4};"
                     :: "l"(dst + idx),
                        "f"(s.x * v), "f"(s.y * v), "f"(s.z * v), "f"(s.w * v)
                     : "memory");
    }
}

// ---------------------------------------------------------------------------
// Kernel 4: in-place ReLU, float4-vectorized, grid-stride.
// ---------------------------------------------------------------------------
__global__ __launch_bounds__(256)
void relu_kernel(float4* __restrict__ out, long long n4)
{
    long long i = (long long)blockIdx.x * blockDim.x + threadIdx.x;
    long long stride = (long long)gridDim.x * blockDim.x;
    for (; i < n4; i += stride) {
        float4 v = out[i];
        v.x = fmaxf(v.x, 0.f);
        v.y = fmaxf(v.y, 0.f);
        v.z = fmaxf(v.z, 0.f);
        v.w = fmaxf(v.w, 0.f);
        out[i] = v;
    }
}

// ---------------------------------------------------------------------------
// kernel_launch
// Inputs (metadata order): features [N*DIN] f32, weight [DIN*DOUT] f32,
//                          rows [E] int, cols [E] int, vals [E] f32
// ---------------------------------------------------------------------------
extern "C" void kernel_launch(void* const* d_in, const int* in_sizes, int n_in,
                              void* d_out, int out_size)
{
    const float* features = (const float*)d_in[0];
    const float* weight   = (const float*)d_in[1];
    const void*  rows     = d_in[2];
    const void*  cols     = d_in[3];
    const float* vals     = (const float*)d_in[4];
    float* out = (float*)d_out;

    const int M = in_sizes[0] / DIN;         // 100000
    const int E = in_sizes[4];               // 3200000 (vals is fp32 -> exact count)

    // support pointer (device global scratch)
    float* sup = nullptr;
    cudaGetSymbolAddress((void**)&sup, g_support);

    // 0) zero the output (poisoned to 0xAA by the harness)
    cudaMemsetAsync(d_out, 0, (size_t)out_size * sizeof(float), 0);

    // 1) index dtype detection (device-side, deterministic)
    detect_idx_kernel<<<1, 256>>>((const long long*)rows, E);

    // 2) dense projection: support = features @ W
    dim3 gemm_grid(DOUT / 128, (M + 127) / 128);
    sgemm_kernel<<<gemm_grid, 256>>>(features, weight, sup, M);

    // 3) edge scatter with vectorized reductions (1 warp / edge)
    const long long total_warps = E;
    const int warps_per_block = 8;           // 256 threads
    const long long n_blocks = (total_warps + warps_per_block - 1) / warps_per_block;
    scatter_kernel<<<(unsigned)n_blocks, 256>>>(rows, cols, vals, sup, out, E);

    // 4) ReLU
    const long long n4 = (long long)out_size / 4;
    int relu_blocks = (int)((n4 + 255) / 256);
    if (relu_blocks > 65535 * 8) relu_blocks = 65535 * 8;
    relu_kernel<<<relu_blocks, 256>>>((float4*)out, n4);
}

// round 2
// speedup vs baseline: 1.3462x; 1.3462x over previous
#include <cuda_runtime.h>
#include <cuda_bf16.h>
#include <cstdint>

// Problem constants (fixed by the reference)
#define NN    100000      // nodes
#define DIN   512
#define DOUT  512

// Scratch: support = features @ W   (200 MB, __device__ global per harness rules)
__device__ float g_support[(size_t)NN * DOUT];

// Flag: 1 if rows/cols are int64, 0 if int32 (JAX x64-disabled fallback)
__device__ int g_idx_is64;

// ---------------------------------------------------------------------------
// Kernel 1: detect index dtype. int32 data read as int64 packs two random
// indices -> value >= NN almost surely within 2048 samples.
// ---------------------------------------------------------------------------
__global__ void detect_idx_kernel(const long long* __restrict__ rows, int n_edges)
{
    __shared__ int bad;
    if (threadIdx.x == 0) bad = 0;
    __syncthreads();
    int limit = 2048;
    if (limit > n_edges / 2) limit = n_edges / 2;
    for (int i = threadIdx.x; i < limit; i += blockDim.x) {
        long long v = rows[i];
        if (v < 0 || v >= NN) bad = 1;
    }
    __syncthreads();
    if (threadIdx.x == 0) g_idx_is64 = bad ? 0 : 1;
}

// ---------------------------------------------------------------------------
// Kernel 2: TF32 tensor-core GEMM  C[M,512] = A[M,512] * B[512,512]
// BM=128, BN=128, BK=32, 8 warps (2 M x 4 N), warp tile 64x32.
// mma.sync.aligned.m16n8k8.row.col.f32.tf32.tf32.f32
// cp.async double-buffered global->smem pipeline. HW tf32 mma ignores the
// low 13 mantissa bits, so raw fp32 bits are valid tf32 operands.
// ---------------------------------------------------------------------------
#define AS_STRIDE 36    // words per A row (16B-aligned, conflict-free frags)
#define BS_STRIDE 132   // words per B row
#define A_BUF_WORDS (128 * AS_STRIDE)        // 4608
#define B_BUF_WORDS (32 * BS_STRIDE)         // 4224
#define SMEM_WORDS  (2 * A_BUF_WORDS + 2 * B_BUF_WORDS)   // 17664 (~69KB)

__device__ __forceinline__ void cp_async16(uint32_t saddr, const void* gptr, int src_bytes)
{
    asm volatile("cp.async.cg.shared.global [%0], [%1], 16, %2;\n"
                 :: "r"(saddr), "l"(gptr), "r"(src_bytes));
}

__global__ __launch_bounds__(256, 2)
void gemm_tf32_kernel(const float* __restrict__ A, const float* __restrict__ B,
                      float* __restrict__ C, int M)
{
    extern __shared__ uint32_t smem[];
    const int tid  = threadIdx.x;
    const int wid  = tid >> 5;
    const int lane = tid & 31;
    const int gid  = lane >> 2;   // groupID 0..7
    const int tg   = lane & 3;    // threadInGroup 0..3

    const int blockRow = blockIdx.y * 128;
    const int blockCol = blockIdx.x * 128;

    // A tile load mapping: each thread 4 x float4 (rows tid/8 + 32*i, k = (tid%8)*4)
    const int aRowL = tid >> 3;           // 0..31
    const int aColL = (tid & 7) * 4;      // word col within 32-k chunk
    // B tile load mapping: each thread 4 x float4 (k rows tid/32 + 8*i, n = (tid%32)*4)
    const int bRowL = tid >> 5;           // 0..7
    const int bColL = (tid & 31) * 4;

    // smem base addresses (bytes) for cp.async
    uint32_t smem_base;
    asm("{ .reg .u64 t; cvta.to.shared.u64 t, %1; cvt.u32.u64 %0, t; }"
        : "=r"(smem_base) : "l"(smem));

    const int warpM = (wid & 1) * 64;
    const int warpN = (wid >> 1) * 32;

    float acc[4][4][4];
#pragma unroll
    for (int i = 0; i < 4; i++)
#pragma unroll
        for (int j = 0; j < 4; j++)
#pragma unroll
            for (int t = 0; t < 4; t++) acc[i][j][t] = 0.f;

    auto issue_chunk = [&](int chunk, int buf) {
        // A: 128 rows x 32 k
#pragma unroll
        for (int i = 0; i < 4; i++) {
            int r = aRowL + 32 * i;
            long long gRow = (long long)blockRow + r;
            bool ok = gRow < M;
            const float* src = A + (ok ? gRow : 0) * DIN + chunk * 32 + aColL;
            uint32_t dst = smem_base + (buf * A_BUF_WORDS + r * AS_STRIDE + aColL) * 4;
            cp_async16(dst, src, ok ? 16 : 0);
        }
        // B: 32 k rows x 128 n
#pragma unroll
        for (int i = 0; i < 4; i++) {
            int kr = bRowL + 8 * i;
            const float* src = B + (long long)(chunk * 32 + kr) * DOUT + blockCol + bColL;
            uint32_t dst = smem_base +
                (2 * A_BUF_WORDS + buf * B_BUF_WORDS + kr * BS_STRIDE + bColL) * 4;
            cp_async16(dst, src, 16);
        }
        asm volatile("cp.async.commit_group;");
    };

    issue_chunk(0, 0);

    const int NCHUNK = DIN / 32;  // 16
    int buf = 0;
    for (int c = 0; c < NCHUNK; c++) {
        if (c + 1 < NCHUNK) {
            issue_chunk(c + 1, buf ^ 1);
            asm volatile("cp.async.wait_group 1;");
        } else {
            asm volatile("cp.async.wait_group 0;");
        }
        __syncthreads();

        const uint32_t* As = smem + buf * A_BUF_WORDS;
        const uint32_t* Bs = smem + 2 * A_BUF_WORDS + buf * B_BUF_WORDS;

#pragma unroll
        for (int ks = 0; ks < 4; ks++) {
            const int kk = ks * 8;
            uint32_t afr[4][4], bfr[4][2];
#pragma unroll
            for (int i = 0; i < 4; i++) {
                int r0 = warpM + i * 16 + gid;
                afr[i][0] = As[(r0)     * AS_STRIDE + kk + tg];
                afr[i][1] = As[(r0 + 8) * AS_STRIDE + kk + tg];
                afr[i][2] = As[(r0)     * AS_STRIDE + kk + tg + 4];
                afr[i][3] = As[(r0 + 8) * AS_STRIDE + kk + tg + 4];
            }
#pragma unroll
            for (int j = 0; j < 4; j++) {
                int cn = warpN + j * 8 + gid;
                bfr[j][0] = Bs[(kk + tg)     * BS_STRIDE + cn];
                bfr[j][1] = Bs[(kk + tg + 4) * BS_STRIDE + cn];
            }
#pragma unroll
            for (int i = 0; i < 4; i++)
#pragma unroll
                for (int j = 0; j < 4; j++) {
                    asm volatile(
                        "mma.sync.aligned.m16n8k8.row.col.f32.tf32.tf32.f32 "
                        "{%0,%1,%2,%3}, {%4,%5,%6,%7}, {%8,%9}, {%0,%1,%2,%3};"
                        : "+f"(acc[i][j][0]), "+f"(acc[i][j][1]),
                          "+f"(acc[i][j][2]), "+f"(acc[i][j][3])
                        : "r"(afr[i][0]), "r"(afr[i][1]), "r"(afr[i][2]), "r"(afr[i][3]),
                          "r"(bfr[j][0]), "r"(bfr[j][1]));
                }
        }
        __syncthreads();
        buf ^= 1;
    }

    // Epilogue: c0,c1 -> (row, col..col+1); c2,c3 -> (row+8, ...)
#pragma unroll
    for (int i = 0; i < 4; i++) {
        long long row0 = (long long)blockRow + warpM + i * 16 + gid;
#pragma unroll
        for (int j = 0; j < 4; j++) {
            int col = blockCol + warpN + j * 8 + tg * 2;
            if (row0 < M) {
                float2 v = make_float2(acc[i][j][0], acc[i][j][1]);
                *(float2*)(C + row0 * DOUT + col) = v;
            }
            if (row0 + 8 < M) {
                float2 v = make_float2(acc[i][j][2], acc[i][j][3]);
                *(float2*)(C + (row0 + 8) * DOUT + col) = v;
            }
        }
    }
}

// ---------------------------------------------------------------------------
// Kernel 3: edge scatter. One warp per edge; red.global.add.v4.f32.
// ---------------------------------------------------------------------------
__global__ __launch_bounds__(256)
void scatter_kernel(const void* __restrict__ rows_, const void* __restrict__ cols_,
                    const float* __restrict__ vals, const float* __restrict__ sup,
                    float* __restrict__ out, int n_edges)
{
    const long long gwarp = ((long long)blockIdx.x * blockDim.x + threadIdx.x) >> 5;
    if (gwarp >= n_edges) return;
    const int lane = threadIdx.x & 31;
    const int e = (int)gwarp;

    long long r, c;
    if (g_idx_is64) {
        r = ((const long long*)rows_)[e];
        c = ((const long long*)cols_)[e];
    } else {
        r = (long long)((const int*)rows_)[e];
        c = (long long)((const int*)cols_)[e];
    }
    const float v = vals[e];

    const float4* __restrict__ src = (const float4*)(sup + c * DOUT);
    float4* __restrict__ dst = ((float4*)out) + r * (DOUT / 4);

#pragma unroll
    for (int i = 0; i < 4; i++) {
        const int idx = lane + i * 32;
        float4 s = src[idx];
        asm volatile("red.global.add.v4.f32 [%0], {%1, %2, %3, %4};"
                     :: "l"(dst + idx),
                        "f"(s.x * v), "f"(s.y * v), "f"(s.z * v), "f"(s.w * v)
                     : "memory");
    }
}

// ---------------------------------------------------------------------------
// Kernel 4: in-place ReLU, float4-vectorized, grid-stride.
// ---------------------------------------------------------------------------
__global__ __launch_bounds__(256)
void relu_kernel(float4* __restrict__ out, long long n4)
{
    long long i = (long long)blockIdx.x * blockDim.x + threadIdx.x;
    long long stride = (long long)gridDim.x * blockDim.x;
    for (; i < n4; i += stride) {
        float4 v = out[i];
        v.x = fmaxf(v.x, 0.f);
        v.y = fmaxf(v.y, 0.f);
        v.z = fmaxf(v.z, 0.f);
        v.w = fmaxf(v.w, 0.f);
        out[i] = v;
    }
}

// ---------------------------------------------------------------------------
// kernel_launch
// ---------------------------------------------------------------------------
extern "C" void kernel_launch(void* const* d_in, const int* in_sizes, int n_in,
                              void* d_out, int out_size)
{
    const float* features = (const float*)d_in[0];
    const float* weight   = (const float*)d_in[1];
    const void*  rows     = d_in[2];
    const void*  cols     = d_in[3];
    const float* vals     = (const float*)d_in[4];
    float* out = (float*)d_out;

    const int M = in_sizes[0] / DIN;         // 100000
    const int E = in_sizes[4];               // 3200000

    float* sup = nullptr;
    cudaGetSymbolAddress((void**)&sup, g_support);

    // 0) zero the output (poisoned to 0xAA by the harness)
    cudaMemsetAsync(d_out, 0, (size_t)out_size * sizeof(float), 0);

    // 1) index dtype detection
    detect_idx_kernel<<<1, 256>>>((const long long*)rows, E);

    // 2) dense projection on tensor cores (tf32)
    static bool attr_set = false;
    if (!attr_set) {
        cudaFuncSetAttribute(gemm_tf32_kernel,
                             cudaFuncAttributeMaxDynamicSharedMemorySize,
                             SMEM_WORDS * 4);
        attr_set = true;
    }
    dim3 gemm_grid(DOUT / 128, (M + 127) / 128);
    gemm_tf32_kernel<<<gemm_grid, 256, SMEM_WORDS * 4>>>(features, weight, sup, M);

    // 3) edge scatter (1 warp / edge)
    const long long n_blocks = ((long long)E + 7) / 8;   // 8 warps per 256-thread block
    scatter_kernel<<<(unsigned)n_blocks, 256>>>(rows, cols, vals, sup, out, E);

    // 4) ReLU
    const long long n4 = (long long)out_size / 4;
    int relu_blocks = (int)((n4 + 255) / 256);
    if (relu_blocks > 65535 * 8) relu_blocks = 65535 * 8;
    relu_kernel<<<relu_blocks, 256>>>((float4*)out, n4);
}

// round 3
// speedup vs baseline: 3.3531x; 2.4908x over previous
#include <cuda_runtime.h>
#include <cuda_bf16.h>
#include <cstdint>

// Problem constants (fixed by the reference)
#define NN    100000      // nodes
#define DIN   512
#define DOUT  512
#define EMAX  3200000     // edges

// Scratch (device globals per harness alloc rules)
__device__ float g_support[(size_t)NN * DOUT];     // 200 MB
__device__ int   g_counts [NN];
__device__ int   g_offsets[NN + 1];
__device__ int   g_cursor [NN];
__device__ int   g_blocksums[128];
__device__ int   g_ecol[EMAX];                     // cols reordered CSR
__device__ float g_eval[EMAX];                     // vals reordered CSR
__device__ int   g_idx_is64;

#define SCAN_ELEMS 1024                             // elements per scan block
#define SCAN_NB   ((NN + SCAN_ELEMS - 1) / SCAN_ELEMS)   // 98

// ---------------------------------------------------------------------------
// Kernel: detect index dtype (int64 vs int32-packed).
// ---------------------------------------------------------------------------
__global__ void detect_idx_kernel(const long long* __restrict__ rows, int n_edges)
{
    __shared__ int bad;
    if (threadIdx.x == 0) bad = 0;
    __syncthreads();
    int limit = 2048;
    if (limit > n_edges / 2) limit = n_edges / 2;
    for (int i = threadIdx.x; i < limit; i += blockDim.x) {
        long long v = rows[i];
        if (v < 0 || v >= NN) bad = 1;
    }
    __syncthreads();
    if (threadIdx.x == 0) g_idx_is64 = bad ? 0 : 1;
}

__device__ __forceinline__ long long load_idx(const void* p, int e)
{
    if (g_idx_is64) return ((const long long*)p)[e];
    return (long long)((const int*)p)[e];
}

// ---------------------------------------------------------------------------
// CSR build, phase 1: histogram of destination rows.
// ---------------------------------------------------------------------------
__global__ __launch_bounds__(256)
void hist_kernel(const void* __restrict__ rows, int E)
{
    int stride = gridDim.x * blockDim.x;
    for (int e = blockIdx.x * blockDim.x + threadIdx.x; e < E; e += stride) {
        int r = (int)load_idx(rows, e);
        atomicAdd(&g_counts[r], 1);
    }
}

// ---------------------------------------------------------------------------
// CSR build, phase 2a: per-scan-block sums (1024 counts each).
// ---------------------------------------------------------------------------
__global__ __launch_bounds__(256)
void scan_blocksum_kernel()
{
    __shared__ int sh[256];
    int b = blockIdx.x, t = threadIdx.x;
    int base = b * SCAN_ELEMS + t * 4;
    int s = 0;
#pragma unroll
    for (int i = 0; i < 4; i++) {
        int idx = base + i;
        if (idx < NN) s += g_counts[idx];
    }
    sh[t] = s; __syncthreads();
    for (int off = 128; off > 0; off >>= 1) {
        if (t < off) sh[t] += sh[t + off];
        __syncthreads();
    }
    if (t == 0) g_blocksums[b] = sh[0];
}

// ---------------------------------------------------------------------------
// CSR build, phase 2b: exclusive scan of the 98 block sums (1 block, serial).
// ---------------------------------------------------------------------------
__global__ void scan_top_kernel(int E)
{
    if (threadIdx.x == 0) {
        int run = 0;
        for (int i = 0; i < SCAN_NB; i++) {
            int v = g_blocksums[i];
            g_blocksums[i] = run;
            run += v;
        }
        g_offsets[NN] = E;
    }
}

// ---------------------------------------------------------------------------
// CSR build, phase 2c: per-block exclusive scan -> offsets, cursor.
// ---------------------------------------------------------------------------
__global__ __launch_bounds__(256)
void scan_write_kernel()
{
    __shared__ int sh[256];
    int b = blockIdx.x, t = threadIdx.x;
    int base = b * SCAN_ELEMS + t * 4;
    int v[4];
#pragma unroll
    for (int i = 0; i < 4; i++)
        v[i] = (base + i < NN) ? g_counts[base + i] : 0;
    int s = v[0] + v[1] + v[2] + v[3];
    sh[t] = s; __syncthreads();
    // Hillis-Steele inclusive scan over 256 thread sums
    for (int off = 1; off < 256; off <<= 1) {
        int x = (t >= off) ? sh[t - off] : 0;
        __syncthreads();
        sh[t] += x;
        __syncthreads();
    }
    int excl = sh[t] - s + g_blocksums[b];
#pragma unroll
    for (int i = 0; i < 4; i++) {
        int idx = base + i;
        if (idx < NN) {
            g_offsets[idx] = excl;
            g_cursor[idx]  = excl;
        }
        excl += v[i];
    }
}

// ---------------------------------------------------------------------------
// CSR build, phase 3: permute (col, val) pairs into CSR slots.
// ---------------------------------------------------------------------------
__global__ __launch_bounds__(256)
void bucket_kernel(const void* __restrict__ rows, const void* __restrict__ cols,
                   const float* __restrict__ vals, int E)
{
    int stride = gridDim.x * blockDim.x;
    for (int e = blockIdx.x * blockDim.x + threadIdx.x; e < E; e += stride) {
        int r = (int)load_idx(rows, e);
        int c = (int)load_idx(cols, e);
        int pos = atomicAdd(&g_cursor[r], 1);
        g_ecol[pos] = c;
        g_eval[pos] = vals[e];
    }
}

// ---------------------------------------------------------------------------
// Aggregation: one block (128 thr) per node. Each thread owns one float4 of
// the 512-wide output row; accumulate over the node's edges in registers,
// fuse ReLU, write once. No atomics, no output memset.
// ---------------------------------------------------------------------------
__global__ __launch_bounds__(128)
void aggregate_kernel(const float* __restrict__ sup, float* __restrict__ out)
{
    const int node = blockIdx.x;
    const int t = threadIdx.x;
    const int beg = g_offsets[node];
    const int end = g_offsets[node + 1];

    __shared__ int   sc[128];
    __shared__ float sv[128];

    float4 acc = make_float4(0.f, 0.f, 0.f, 0.f);

    for (int j0 = beg; j0 < end; j0 += 128) {
        int m = end - j0; if (m > 128) m = 128;
        if (t < m) { sc[t] = g_ecol[j0 + t]; sv[t] = g_eval[j0 + t]; }
        __syncthreads();

        int k = 0;
        // unroll by 4 for MLP
        for (; k + 4 <= m; k += 4) {
            const float4* p0 = (const float4*)(sup + (long long)sc[k + 0] * DOUT) + t;
            const float4* p1 = (const float4*)(sup + (long long)sc[k + 1] * DOUT) + t;
            const float4* p2 = (const float4*)(sup + (long long)sc[k + 2] * DOUT) + t;
            const float4* p3 = (const float4*)(sup + (long long)sc[k + 3] * DOUT) + t;
            float4 s0 = __ldg(p0), s1 = __ldg(p1), s2 = __ldg(p2), s3 = __ldg(p3);
            float v0 = sv[k + 0], v1 = sv[k + 1], v2 = sv[k + 2], v3 = sv[k + 3];
            acc.x += v0 * s0.x; acc.y += v0 * s0.y; acc.z += v0 * s0.z; acc.w += v0 * s0.w;
            acc.x += v1 * s1.x; acc.y += v1 * s1.y; acc.z += v1 * s1.z; acc.w += v1 * s1.w;
            acc.x += v2 * s2.x; acc.y += v2 * s2.y; acc.z += v2 * s2.z; acc.w += v2 * s2.w;
            acc.x += v3 * s3.x; acc.y += v3 * s3.y; acc.z += v3 * s3.z; acc.w += v3 * s3.w;
        }
        for (; k < m; k++) {
            float4 s = __ldg((const float4*)(sup + (long long)sc[k] * DOUT) + t);
            float v = sv[k];
            acc.x += v * s.x; acc.y += v * s.y; acc.z += v * s.z; acc.w += v * s.w;
        }
        __syncthreads();
    }

    acc.x = fmaxf(acc.x, 0.f); acc.y = fmaxf(acc.y, 0.f);
    acc.z = fmaxf(acc.z, 0.f); acc.w = fmaxf(acc.w, 0.f);
    ((float4*)out)[(long long)node * (DOUT / 4) + t] = acc;
}

// ---------------------------------------------------------------------------
// TF32 tensor-core GEMM  C[M,512] = A[M,512] * B[512,512]  (unchanged R2)
// ---------------------------------------------------------------------------
#define AS_STRIDE 36
#define BS_STRIDE 132
#define A_BUF_WORDS (128 * AS_STRIDE)
#define B_BUF_WORDS (32 * BS_STRIDE)
#define SMEM_WORDS  (2 * A_BUF_WORDS + 2 * B_BUF_WORDS)

__device__ __forceinline__ void cp_async16(uint32_t saddr, const void* gptr, int src_bytes)
{
    asm volatile("cp.async.cg.shared.global [%0], [%1], 16, %2;\n"
                 :: "r"(saddr), "l"(gptr), "r"(src_bytes));
}

__global__ __launch_bounds__(256, 2)
void gemm_tf32_kernel(const float* __restrict__ A, const float* __restrict__ B,
                      float* __restrict__ C, int M)
{
    extern __shared__ uint32_t smem[];
    const int tid  = threadIdx.x;
    const int wid  = tid >> 5;
    const int lane = tid & 31;
    const int gid  = lane >> 2;
    const int tg   = lane & 3;

    const int blockRow = blockIdx.y * 128;
    const int blockCol = blockIdx.x * 128;

    const int aRowL = tid >> 3;
    const int aColL = (tid & 7) * 4;
    const int bRowL = tid >> 5;
    const int bColL = (tid & 31) * 4;

    uint32_t smem_base;
    asm("{ .reg .u64 t; cvta.to.shared.u64 t, %1; cvt.u32.u64 %0, t; }"
        : "=r"(smem_base) : "l"(smem));

    const int warpM = (wid & 1) * 64;
    const int warpN = (wid >> 1) * 32;

    float acc[4][4][4];
#pragma unroll
    for (int i = 0; i < 4; i++)
#pragma unroll
        for (int j = 0; j < 4; j++)
#pragma unroll
            for (int t = 0; t < 4; t++) acc[i][j][t] = 0.f;

    auto issue_chunk = [&](int chunk, int buf) {
#pragma unroll
        for (int i = 0; i < 4; i++) {
            int r = aRowL + 32 * i;
            long long gRow = (long long)blockRow + r;
            bool ok = gRow < M;
            const float* src = A + (ok ? gRow : 0) * DIN + chunk * 32 + aColL;
            uint32_t dst = smem_base + (buf * A_BUF_WORDS + r * AS_STRIDE + aColL) * 4;
            cp_async16(dst, src, ok ? 16 : 0);
        }
#pragma unroll
        for (int i = 0; i < 4; i++) {
            int kr = bRowL + 8 * i;
            const float* src = B + (long long)(chunk * 32 + kr) * DOUT + blockCol + bColL;
            uint32_t dst = smem_base +
                (2 * A_BUF_WORDS + buf * B_BUF_WORDS + kr * BS_STRIDE + bColL) * 4;
            cp_async16(dst, src, 16);
        }
        asm volatile("cp.async.commit_group;");
    };

    issue_chunk(0, 0);

    const int NCHUNK = DIN / 32;
    int buf = 0;
    for (int c = 0; c < NCHUNK; c++) {
        if (c + 1 < NCHUNK) {
            issue_chunk(c + 1, buf ^ 1);
            asm volatile("cp.async.wait_group 1;");
        } else {
            asm volatile("cp.async.wait_group 0;");
        }
        __syncthreads();

        const uint32_t* As = smem + buf * A_BUF_WORDS;
        const uint32_t* Bs = smem + 2 * A_BUF_WORDS + buf * B_BUF_WORDS;

#pragma unroll
        for (int ks = 0; ks < 4; ks++) {
            const int kk = ks * 8;
            uint32_t afr[4][4], bfr[4][2];
#pragma unroll
            for (int i = 0; i < 4; i++) {
                int r0 = warpM + i * 16 + gid;
                afr[i][0] = As[(r0)     * AS_STRIDE + kk + tg];
                afr[i][1] = As[(r0 + 8) * AS_STRIDE + kk + tg];
                afr[i][2] = As[(r0)     * AS_STRIDE + kk + tg + 4];
                afr[i][3] = As[(r0 + 8) * AS_STRIDE + kk + tg + 4];
            }
#pragma unroll
            for (int j = 0; j < 4; j++) {
                int cn = warpN + j * 8 + gid;
                bfr[j][0] = Bs[(kk + tg)     * BS_STRIDE + cn];
                bfr[j][1] = Bs[(kk + tg + 4) * BS_STRIDE + cn];
            }
#pragma unroll
            for (int i = 0; i < 4; i++)
#pragma unroll
                for (int j = 0; j < 4; j++) {
                    asm volatile(
                        "mma.sync.aligned.m16n8k8.row.col.f32.tf32.tf32.f32 "
                        "{%0,%1,%2,%3}, {%4,%5,%6,%7}, {%8,%9}, {%0,%1,%2,%3};"
                        : "+f"(acc[i][j][0]), "+f"(acc[i][j][1]),
                          "+f"(acc[i][j][2]), "+f"(acc[i][j][3])
                        : "r"(afr[i][0]), "r"(afr[i][1]), "r"(afr[i][2]), "r"(afr[i][3]),
                          "r"(bfr[j][0]), "r"(bfr[j][1]));
                }
        }
        __syncthreads();
        buf ^= 1;
    }

#pragma unroll
    for (int i = 0; i < 4; i++) {
        long long row0 = (long long)blockRow + warpM + i * 16 + gid;
#pragma unroll
        for (int j = 0; j < 4; j++) {
            int col = blockCol + warpN + j * 8 + tg * 2;
            if (row0 < M)
                *(float2*)(C + row0 * DOUT + col) = make_float2(acc[i][j][0], acc[i][j][1]);
            if (row0 + 8 < M)
                *(float2*)(C + (row0 + 8) * DOUT + col) = make_float2(acc[i][j][2], acc[i][j][3]);
        }
    }
}

// ---------------------------------------------------------------------------
// kernel_launch
// ---------------------------------------------------------------------------
extern "C" void kernel_launch(void* const* d_in, const int* in_sizes, int n_in,
                              void* d_out, int out_size)
{
    const float* features = (const float*)d_in[0];
    const float* weight   = (const float*)d_in[1];
    const void*  rows     = d_in[2];
    const void*  cols     = d_in[3];
    const float* vals     = (const float*)d_in[4];
    float* out = (float*)d_out;

    const int M = in_sizes[0] / DIN;   // 100000
    const int E = in_sizes[4];         // 3200000

    float* sup = nullptr;
    cudaGetSymbolAddress((void**)&sup, g_support);
    int* counts_ptr = nullptr;
    cudaGetSymbolAddress((void**)&counts_ptr, g_counts);

    // 0) zero the histogram
    cudaMemsetAsync(counts_ptr, 0, (size_t)NN * sizeof(int), 0);

    // 1) index dtype detection
    detect_idx_kernel<<<1, 256>>>((const long long*)rows, E);

    // 2) dense projection on tensor cores (tf32) — overlaps nothing, stream 0
    static bool attr_set = false;
    if (!attr_set) {
        cudaFuncSetAttribute(gemm_tf32_kernel,
                             cudaFuncAttributeMaxDynamicSharedMemorySize,
                             SMEM_WORDS * 4);
        attr_set = true;
    }
    dim3 gemm_grid(DOUT / 128, (M + 127) / 128);
    gemm_tf32_kernel<<<gemm_grid, 256, SMEM_WORDS * 4>>>(features, weight, sup, M);

    // 3) CSR build
    hist_kernel<<<2048, 256>>>(rows, E);
    scan_blocksum_kernel<<<SCAN_NB, 256>>>();
    scan_top_kernel<<<1, 32>>>(E);
    scan_write_kernel<<<SCAN_NB, 256>>>();
    bucket_kernel<<<2048, 256>>>(rows, cols, vals, E);

    // 4) aggregation + fused ReLU (one block per node, single write per row)
    aggregate_kernel<<<M, 128>>>(sup, out);
}

// round 4
// speedup vs baseline: 3.4113x; 1.0174x over previous
#include <cuda_runtime.h>
#include <cuda_bf16.h>
#include <cstdint>

// Problem constants (fixed by the reference)
#define NN    100000      // nodes
#define DIN   512
#define DOUT  512
#define EMAX  3200000     // edges

// Scratch (device globals per harness alloc rules)
__device__ float g_support[(size_t)NN * DOUT];     // 200 MB
__device__ int   g_counts [NN];
__device__ int   g_offsets[NN + 1];
__device__ int   g_cursor [NN];
__device__ int   g_blocksums[128];
__device__ int   g_ecol[EMAX];                     // cols reordered CSR
__device__ float g_eval[EMAX];                     // vals reordered CSR
__device__ int   g_idx_is64;

#define SCAN_ELEMS 1024
#define SCAN_NB   ((NN + SCAN_ELEMS - 1) / SCAN_ELEMS)   // 98

// ---------------------------------------------------------------------------
// Kernel: detect index dtype (int64 vs int32-packed).
// ---------------------------------------------------------------------------
__global__ void detect_idx_kernel(const long long* __restrict__ rows, int n_edges)
{
    __shared__ int bad;
    if (threadIdx.x == 0) bad = 0;
    __syncthreads();
    int limit = 2048;
    if (limit > n_edges / 2) limit = n_edges / 2;
    for (int i = threadIdx.x; i < limit; i += blockDim.x) {
        long long v = rows[i];
        if (v < 0 || v >= NN) bad = 1;
    }
    __syncthreads();
    if (threadIdx.x == 0) g_idx_is64 = bad ? 0 : 1;
}

__device__ __forceinline__ long long load_idx(const void* p, int e)
{
    if (g_idx_is64) return ((const long long*)p)[e];
    return (long long)((const int*)p)[e];
}

// ---------------------------------------------------------------------------
// CSR build, phase 1: histogram of destination rows.
// ---------------------------------------------------------------------------
__global__ __launch_bounds__(256)
void hist_kernel(const void* __restrict__ rows, int E)
{
    int stride = gridDim.x * blockDim.x;
    for (int e = blockIdx.x * blockDim.x + threadIdx.x; e < E; e += stride) {
        int r = (int)load_idx(rows, e);
        atomicAdd(&g_counts[r], 1);
    }
}

// ---------------------------------------------------------------------------
// CSR build, phase 2a: per-scan-block sums (1024 counts each).
// ---------------------------------------------------------------------------
__global__ __launch_bounds__(256)
void scan_blocksum_kernel()
{
    __shared__ int sh[256];
    int b = blockIdx.x, t = threadIdx.x;
    int base = b * SCAN_ELEMS + t * 4;
    int s = 0;
#pragma unroll
    for (int i = 0; i < 4; i++) {
        int idx = base + i;
        if (idx < NN) s += g_counts[idx];
    }
    sh[t] = s; __syncthreads();
    for (int off = 128; off > 0; off >>= 1) {
        if (t < off) sh[t] += sh[t + off];
        __syncthreads();
    }
    if (t == 0) g_blocksums[b] = sh[0];
}

// ---------------------------------------------------------------------------
// CSR build, phase 2b: exclusive scan of the 98 block sums (1 block, serial).
// ---------------------------------------------------------------------------
__global__ void scan_top_kernel(int E)
{
    if (threadIdx.x == 0) {
        int run = 0;
        for (int i = 0; i < SCAN_NB; i++) {
            int v = g_blocksums[i];
            g_blocksums[i] = run;
            run += v;
        }
        g_offsets[NN] = E;
    }
}

// ---------------------------------------------------------------------------
// CSR build, phase 2c: per-block exclusive scan -> offsets, cursor.
// ---------------------------------------------------------------------------
__global__ __launch_bounds__(256)
void scan_write_kernel()
{
    __shared__ int sh[256];
    int b = blockIdx.x, t = threadIdx.x;
    int base = b * SCAN_ELEMS + t * 4;
    int v[4];
#pragma unroll
    for (int i = 0; i < 4; i++)
        v[i] = (base + i < NN) ? g_counts[base + i] : 0;
    int s = v[0] + v[1] + v[2] + v[3];
    sh[t] = s; __syncthreads();
    for (int off = 1; off < 256; off <<= 1) {
        int x = (t >= off) ? sh[t - off] : 0;
        __syncthreads();
        sh[t] += x;
        __syncthreads();
    }
    int excl = sh[t] - s + g_blocksums[b];
#pragma unroll
    for (int i = 0; i < 4; i++) {
        int idx = base + i;
        if (idx < NN) {
            g_offsets[idx] = excl;
            g_cursor[idx]  = excl;
        }
        excl += v[i];
    }
}

// ---------------------------------------------------------------------------
// CSR build, phase 3: permute (col, val) pairs into CSR slots.
// ---------------------------------------------------------------------------
__global__ __launch_bounds__(256)
void bucket_kernel(const void* __restrict__ rows, const void* __restrict__ cols,
                   const float* __restrict__ vals, int E)
{
    int stride = gridDim.x * blockDim.x;
    for (int e = blockIdx.x * blockDim.x + threadIdx.x; e < E; e += stride) {
        int r = (int)load_idx(rows, e);
        int c = (int)load_idx(cols, e);
        int pos = atomicAdd(&g_cursor[r], 1);
        g_ecol[pos] = c;
        g_eval[pos] = vals[e];
    }
}

// ---------------------------------------------------------------------------
// Aggregation: one block (128 thr) per node, register accumulation, fused ReLU.
// ---------------------------------------------------------------------------
__global__ __launch_bounds__(128)
void aggregate_kernel(const float* __restrict__ sup, float* __restrict__ out)
{
    const int node = blockIdx.x;
    const int t = threadIdx.x;
    const int beg = g_offsets[node];
    const int end = g_offsets[node + 1];

    __shared__ int   sc[128];
    __shared__ float sv[128];

    float4 acc = make_float4(0.f, 0.f, 0.f, 0.f);

    for (int j0 = beg; j0 < end; j0 += 128) {
        int m = end - j0; if (m > 128) m = 128;
        if (t < m) { sc[t] = g_ecol[j0 + t]; sv[t] = g_eval[j0 + t]; }
        __syncthreads();

        int k = 0;
        for (; k + 4 <= m; k += 4) {
            const float4* p0 = (const float4*)(sup + (long long)sc[k + 0] * DOUT) + t;
            const float4* p1 = (const float4*)(sup + (long long)sc[k + 1] * DOUT) + t;
            const float4* p2 = (const float4*)(sup + (long long)sc[k + 2] * DOUT) + t;
            const float4* p3 = (const float4*)(sup + (long long)sc[k + 3] * DOUT) + t;
            float4 s0 = __ldg(p0), s1 = __ldg(p1), s2 = __ldg(p2), s3 = __ldg(p3);
            float v0 = sv[k + 0], v1 = sv[k + 1], v2 = sv[k + 2], v3 = sv[k + 3];
            acc.x += v0 * s0.x; acc.y += v0 * s0.y; acc.z += v0 * s0.z; acc.w += v0 * s0.w;
            acc.x += v1 * s1.x; acc.y += v1 * s1.y; acc.z += v1 * s1.z; acc.w += v1 * s1.w;
            acc.x += v2 * s2.x; acc.y += v2 * s2.y; acc.z += v2 * s2.z; acc.w += v2 * s2.w;
            acc.x += v3 * s3.x; acc.y += v3 * s3.y; acc.z += v3 * s3.z; acc.w += v3 * s3.w;
        }
        for (; k < m; k++) {
            float4 s = __ldg((const float4*)(sup + (long long)sc[k] * DOUT) + t);
            float v = sv[k];
            acc.x += v * s.x; acc.y += v * s.y; acc.z += v * s.z; acc.w += v * s.w;
        }
        __syncthreads();
    }

    acc.x = fmaxf(acc.x, 0.f); acc.y = fmaxf(acc.y, 0.f);
    acc.z = fmaxf(acc.z, 0.f); acc.w = fmaxf(acc.w, 0.f);
    ((float4*)out)[(long long)node * (DOUT / 4) + t] = acc;
}

// ---------------------------------------------------------------------------
// TF32 tensor-core GEMM  C[M,512] = A[M,512] * B[512,512]  (unchanged R2/R3)
// ---------------------------------------------------------------------------
#define AS_STRIDE 36
#define BS_STRIDE 132
#define A_BUF_WORDS (128 * AS_STRIDE)
#define B_BUF_WORDS (32 * BS_STRIDE)
#define SMEM_WORDS  (2 * A_BUF_WORDS + 2 * B_BUF_WORDS)

__device__ __forceinline__ void cp_async16(uint32_t saddr, const void* gptr, int src_bytes)
{
    asm volatile("cp.async.cg.shared.global [%0], [%1], 16, %2;\n"
                 :: "r"(saddr), "l"(gptr), "r"(src_bytes));
}

__global__ __launch_bounds__(256, 2)
void gemm_tf32_kernel(const float* __restrict__ A, const float* __restrict__ B,
                      float* __restrict__ C, int M)
{
    extern __shared__ uint32_t smem[];
    const int tid  = threadIdx.x;
    const int wid  = tid >> 5;
    const int lane = tid & 31;
    const int gid  = lane >> 2;
    const int tg   = lane & 3;

    const int blockRow = blockIdx.y * 128;
    const int blockCol = blockIdx.x * 128;

    const int aRowL = tid >> 3;
    const int aColL = (tid & 7) * 4;
    const int bRowL = tid >> 5;
    const int bColL = (tid & 31) * 4;

    uint32_t smem_base;
    asm("{ .reg .u64 t; cvta.to.shared.u64 t, %1; cvt.u32.u64 %0, t; }"
        : "=r"(smem_base) : "l"(smem));

    const int warpM = (wid & 1) * 64;
    const int warpN = (wid >> 1) * 32;

    float acc[4][4][4];
#pragma unroll
    for (int i = 0; i < 4; i++)
#pragma unroll
        for (int j = 0; j < 4; j++)
#pragma unroll
            for (int t = 0; t < 4; t++) acc[i][j][t] = 0.f;

    auto issue_chunk = [&](int chunk, int buf) {
#pragma unroll
        for (int i = 0; i < 4; i++) {
            int r = aRowL + 32 * i;
            long long gRow = (long long)blockRow + r;
            bool ok = gRow < M;
            const float* src = A + (ok ? gRow : 0) * DIN + chunk * 32 + aColL;
            uint32_t dst = smem_base + (buf * A_BUF_WORDS + r * AS_STRIDE + aColL) * 4;
            cp_async16(dst, src, ok ? 16 : 0);
        }
#pragma unroll
        for (int i = 0; i < 4; i++) {
            int kr = bRowL + 8 * i;
            const float* src = B + (long long)(chunk * 32 + kr) * DOUT + blockCol + bColL;
            uint32_t dst = smem_base +
                (2 * A_BUF_WORDS + buf * B_BUF_WORDS + kr * BS_STRIDE + bColL) * 4;
            cp_async16(dst, src, 16);
        }
        asm volatile("cp.async.commit_group;");
    };

    issue_chunk(0, 0);

    const int NCHUNK = DIN / 32;
    int buf = 0;
    for (int c = 0; c < NCHUNK; c++) {
        if (c + 1 < NCHUNK) {
            issue_chunk(c + 1, buf ^ 1);
            asm volatile("cp.async.wait_group 1;");
        } else {
            asm volatile("cp.async.wait_group 0;");
        }
        __syncthreads();

        const uint32_t* As = smem + buf * A_BUF_WORDS;
        const uint32_t* Bs = smem + 2 * A_BUF_WORDS + buf * B_BUF_WORDS;

#pragma unroll
        for (int ks = 0; ks < 4; ks++) {
            const int kk = ks * 8;
            uint32_t afr[4][4], bfr[4][2];
#pragma unroll
            for (int i = 0; i < 4; i++) {
                int r0 = warpM + i * 16 + gid;
                afr[i][0] = As[(r0)     * AS_STRIDE + kk + tg];
                afr[i][1] = As[(r0 + 8) * AS_STRIDE + kk + tg];
                afr[i][2] = As[(r0)     * AS_STRIDE + kk + tg + 4];
                afr[i][3] = As[(r0 + 8) * AS_STRIDE + kk + tg + 4];
            }
#pragma unroll
            for (int j = 0; j < 4; j++) {
                int cn = warpN + j * 8 + gid;
                bfr[j][0] = Bs[(kk + tg)     * BS_STRIDE + cn];
                bfr[j][1] = Bs[(kk + tg + 4) * BS_STRIDE + cn];
            }
#pragma unroll
            for (int i = 0; i < 4; i++)
#pragma unroll
                for (int j = 0; j < 4; j++) {
                    asm volatile(
                        "mma.sync.aligned.m16n8k8.row.col.f32.tf32.tf32.f32 "
                        "{%0,%1,%2,%3}, {%4,%5,%6,%7}, {%8,%9}, {%0,%1,%2,%3};"
                        : "+f"(acc[i][j][0]), "+f"(acc[i][j][1]),
                          "+f"(acc[i][j][2]), "+f"(acc[i][j][3])
                        : "r"(afr[i][0]), "r"(afr[i][1]), "r"(afr[i][2]), "r"(afr[i][3]),
                          "r"(bfr[j][0]), "r"(bfr[j][1]));
                }
        }
        __syncthreads();
        buf ^= 1;
    }

#pragma unroll
    for (int i = 0; i < 4; i++) {
        long long row0 = (long long)blockRow + warpM + i * 16 + gid;
#pragma unroll
        for (int j = 0; j < 4; j++) {
            int col = blockCol + warpN + j * 8 + tg * 2;
            if (row0 < M)
                *(float2*)(C + row0 * DOUT + col) = make_float2(acc[i][j][0], acc[i][j][1]);
            if (row0 + 8 < M)
                *(float2*)(C + (row0 + 8) * DOUT + col) = make_float2(acc[i][j][2], acc[i][j][3]);
        }
    }
}

// ---------------------------------------------------------------------------
// kernel_launch: fork/join two branches inside graph capture.
//   branch A (capture stream 0): tf32 GEMM
//   branch B (non-blocking side stream): CSR build (memset/detect/hist/scan/bucket)
// Join, then aggregation (needs both).
// ---------------------------------------------------------------------------
extern "C" void kernel_launch(void* const* d_in, const int* in_sizes, int n_in,
                              void* d_out, int out_size)
{
    const float* features = (const float*)d_in[0];
    const float* weight   = (const float*)d_in[1];
    const void*  rows     = d_in[2];
    const void*  cols     = d_in[3];
    const float* vals     = (const float*)d_in[4];
    float* out = (float*)d_out;

    const int M = in_sizes[0] / DIN;   // 100000
    const int E = in_sizes[4];         // 3200000

    float* sup = nullptr;
    cudaGetSymbolAddress((void**)&sup, g_support);
    int* counts_ptr = nullptr;
    cudaGetSymbolAddress((void**)&counts_ptr, g_counts);

    // One-time host-side setup (no device allocations).
    static bool init_done = false;
    static cudaStream_t s1;
    static cudaEvent_t ev_fork, ev_join;
    if (!init_done) {
        cudaFuncSetAttribute(gemm_tf32_kernel,
                             cudaFuncAttributeMaxDynamicSharedMemorySize,
                             SMEM_WORDS * 4);
        cudaStreamCreateWithFlags(&s1, cudaStreamNonBlocking);
        cudaEventCreateWithFlags(&ev_fork, cudaEventDisableTiming);
        cudaEventCreateWithFlags(&ev_join, cudaEventDisableTiming);
        init_done = true;
    }

    // ---- fork ----
    cudaEventRecord(ev_fork, 0);
    cudaStreamWaitEvent(s1, ev_fork, 0);

    // Branch B (side stream): CSR build
    cudaMemsetAsync(counts_ptr, 0, (size_t)NN * sizeof(int), s1);
    detect_idx_kernel<<<1, 256, 0, s1>>>((const long long*)rows, E);
    hist_kernel<<<2048, 256, 0, s1>>>(rows, E);
    scan_blocksum_kernel<<<SCAN_NB, 256, 0, s1>>>();
    scan_top_kernel<<<1, 32, 0, s1>>>(E);
    scan_write_kernel<<<SCAN_NB, 256, 0, s1>>>();
    bucket_kernel<<<2048, 256, 0, s1>>>(rows, cols, vals, E);
    cudaEventRecord(ev_join, s1);

    // Branch A (capture stream): dense projection on tensor cores (tf32)
    dim3 gemm_grid(DOUT / 128, (M + 127) / 128);
    gemm_tf32_kernel<<<gemm_grid, 256, SMEM_WORDS * 4>>>(features, weight, sup, M);

    // ---- join ----
    cudaStreamWaitEvent(0, ev_join, 0);

    // Aggregation + fused ReLU (needs support + CSR)
    aggregate_kernel<<<M, 128>>>(sup, out);
}